// round 8
// baseline (speedup 1.0000x reference)
#include <cuda_runtime.h>

#define T_STEPS 2048
#define BATCH   256
#define HID     128
#define NTHREADS 512
#define GHS     392      // ghs row stride (floats)
#define HSW     144      // swizzled h stride per batch

typedef unsigned long long u64;

__device__ __forceinline__ u64 ffma2(u64 a, u64 b, u64 c) {
    u64 d;
    asm("fma.rn.f32x2 %0, %1, %2, %3;" : "=l"(d) : "l"(a), "l"(b), "l"(c));
    return d;
}
__device__ __forceinline__ float hsum2(u64 v) {
    float x, y;
    asm("mov.b64 {%0, %1}, %2;" : "=f"(x), "=f"(y) : "l"(v));
    return x + y;
}
#define BARS(id, cnt) asm volatile("bar.sync %0, %1;"   :: "r"(id), "r"(cnt) : "memory")
#define BARA(id, cnt) asm volatile("bar.arrive %0, %1;" :: "r"(id), "r"(cnt) : "memory")
// Barriers: G0=1 (384 arr w4-15 + 128 sync w0-3), G1=2 (384 arr w0-3,w8-15 + 128 sync w4-7)
//           H0a=3 (128 arr w0-3 + 256 sync w8-15), H0b=4 (128 arr w0-3 + 128 sync w4-7)
//           H1a=5 (128 arr w4-7 + 256 sync w8-15), H1b=6 (128 arr w4-7 + 128 sync w0-3)

// A-phase: 3 row-dots from register weights, 4-shfl multi-value reduce, 1 predicated STS
#define A_PHASE(HB, PA)                                                          \
    {                                                                            \
        u64 q0 = 0ull, q1 = 0ull, q2 = 0ull;                                     \
        _Pragma("unroll")                                                        \
        for (int c = 0; c < 8; ++c) {                                            \
            ulonglong2 hv = (HB)[c];                                             \
            q0 = ffma2(wr0[2 * c],     hv.x, q0);                                \
            q1 = ffma2(wr1[2 * c],     hv.x, q1);                                \
            q2 = ffma2(wr2[2 * c],     hv.x, q2);                                \
            q0 = ffma2(wr0[2 * c + 1], hv.y, q0);                                \
            q1 = ffma2(wr1[2 * c + 1], hv.y, q1);                                \
            q2 = ffma2(wr2[2 * c + 1], hv.y, q2);                                \
        }                                                                        \
        float f0 = hsum2(q0), f1 = hsum2(q1), f2 = hsum2(q2);                    \
        float snd = (ks & 1) ? f0 : f1;                                          \
        float kp  = (ks & 1) ? f1 : f0;                                          \
        float av  = kp + __shfl_xor_sync(0xffffffffu, snd, 1);                   \
        float cv  = f2 + __shfl_xor_sync(0xffffffffu, f2, 1);                    \
        float resA = av + __shfl_xor_sync(0xffffffffu, av, 2);                   \
        float resC = cv + __shfl_xor_sync(0xffffffffu, cv, 2);                   \
        if (ks < 3) (PA)[0] = (ks < 2) ? resA : resC;                            \
    }
// lane ks: 0 -> row r0 (f0 total), 1 -> r0+8 (f1), 2 -> r0+16 (f2), 3 -> no store

// B-phase for this thread's (batch, unit); consts from smem, h in register
#define B_PHASE(BB, TB)                                                          \
    {                                                                            \
        const float* gh = ghs + (BB) * GHS;                                      \
        float xh = xpart[(BB)*4] + xpart[(BB)*4+1] + xpart[(BB)*4+2]             \
                 + xpart[(BB)*4+3] + cons[5 * HID];                              \
        float xt = xn;                                                           \
        if ((TB) + 1 < T_STEPS) xn = __ldg(x + (size_t)(b0 + (BB)) * T_STEPS + (TB) + 1); \
        float cur = ((TB) == 0) ? xt : ((xt == 128.0f) ? xh : xt);               \
        float gr  = fmaf(cur, wihs[ub],           cons[ub])           + gh[ub];  \
        float gz  = fmaf(cur, wihs[ub + HID],     cons[ub + HID])     + gh[ub + 128]; \
        float gni = fmaf(cur, wihs[ub + 2 * HID], cons[ub + 2 * HID]);           \
        float rr  = __fdividef(1.0f, 1.0f + __expf(-gr));                        \
        float zz  = __fdividef(1.0f, 1.0f + __expf(-gz));                        \
        float na  = fmaf(rr, gh[ub + 256] + cons[ub + 3 * HID], gni);            \
        float e2  = __expf(2.0f * na);                                           \
        float nn  = 1.0f - __fdividef(2.0f, e2 + 1.0f);                          \
        float hnew = fmaf(zz, hreg - nn, nn);                                    \
        hreg = hnew;                                                             \
        hsw[(BB) * HSW + ub + (ub >> 5) * 4] = hnew;                             \
        if (ub == 0) {                                                           \
            out[(TB) * BATCH + b0 + (BB)] = cur;                                 \
            if ((TB) > 0) out[T_STEPS * BATCH + (size_t)(b0 + (BB)) * (T_STEPS - 1) + (TB) - 1] = xh; \
        }                                                                        \
        float p = hnew * cons[4 * HID + ub];                                     \
        _Pragma("unroll")                                                        \
        for (int off = 16; off >= 1; off >>= 1)                                  \
            p += __shfl_xor_sync(0xffffffffu, p, off);                           \
        if (lane == 0) xpart[(BB) * 4 + (wrp & 3)] = p;                          \
    }

__global__ void __launch_bounds__(NTHREADS, 1)
gru_impute_kernel(const float* __restrict__ x,     // [B, T] (I=1)
                  const float* __restrict__ Wih,   // [384, 1]
                  const float* __restrict__ Whh,   // [384, 128]
                  const float* __restrict__ bih,   // [384]
                  const float* __restrict__ bhh,   // [384]
                  const float* __restrict__ Wfc,   // [1, 128]
                  const float* __restrict__ bfc,   // [1]
                  float* __restrict__ out)
{
    extern __shared__ float sm[];
    float* hsw   = sm;                   // 2 * HSW swizzled hidden state
    float* ghs   = sm + 2 * HSW;         // 2 * GHS raw gate dots
    float* xpart = ghs + 2 * GHS;        // 8 x_hat warp partials
    float* wihs  = xpart + 8;            // 384
    float* cons  = wihs + 3 * HID;       // br[128], bz[128], bnI[128], bhn[128], wfc[128], bf

    const int tid  = threadIdx.x;
    const int lane = tid & 31;
    const int wrp  = tid >> 5;           // 0..15
    const int ks   = lane & 3;
    const int g    = lane >> 2;
    const int b0   = blockIdx.x * 2;
    const int r0   = wrp * 24 + g;

    // ---- one-time staging ----
    u64 wr0[16], wr1[16], wr2[16];
    {
        const u64* p0 = reinterpret_cast<const u64*>(Whh + (r0     ) * HID + ks * 32);
        const u64* p1 = reinterpret_cast<const u64*>(Whh + (r0 +  8) * HID + ks * 32);
        const u64* p2 = reinterpret_cast<const u64*>(Whh + (r0 + 16) * HID + ks * 32);
        #pragma unroll
        for (int i = 0; i < 16; ++i) { wr0[i] = __ldg(p0 + i); wr1[i] = __ldg(p1 + i); wr2[i] = __ldg(p2 + i); }
    }
    for (int idx = tid; idx < 2 * HSW; idx += NTHREADS) hsw[idx] = 0.0f;
    if (tid < 8) xpart[tid] = 0.0f;
    for (int idx = tid; idx < 3 * HID; idx += NTHREADS) wihs[idx] = Wih[idx];
    for (int idx = tid; idx < HID; idx += NTHREADS) {
        cons[idx]           = bih[idx]           + bhh[idx];            // br
        cons[idx + HID]     = bih[idx + 128]     + bhh[idx + 128];      // bz
        cons[idx + 2 * HID] = bih[idx + 256];                           // bnI
        cons[idx + 3 * HID] = bhh[idx + 256];                           // bhn
        cons[idx + 4 * HID] = Wfc[idx];                                 // wfc
    }
    if (tid == 0) cons[5 * HID] = bfc[0];

    const ulonglong2* hb0 = reinterpret_cast<const ulonglong2*>(hsw + ks * 36);
    const ulonglong2* hb1 = reinterpret_cast<const ulonglong2*>(hsw + HSW + ks * 36);
    float* paA0 = ghs + r0 + 8 * ks;           // A0 store slot (ks<3)
    float* paA1 = ghs + GHS + r0 + 8 * ks;     // A1 store slot

    const int ub = tid & 127;                  // B-unit for warps 0..7
    float hreg = 0.0f;
    float xn = 0.0f;
    if (wrp < 8) xn = __ldg(x + (size_t)(b0 + (wrp >> 2)) * T_STEPS);
    __syncthreads();

    if (wrp < 4) {
        // ===== warps 0-3: A0, B0, A1 =====
        for (int t = 0; t < T_STEPS; ++t) {
            A_PHASE(hb0, paA0);
            BARS(1, 512);                       // G0: all ghs0(t) visible
            B_PHASE(0, t);                      // overlaps w8-15's A1 + w4-7's A1
            BARA(3, 384); BARA(4, 256);         // H0a, H0b: h0(t) published
            BARS(6, 256);                       // H1b: h1(t-1) ready
            A_PHASE(hb1, paA1);
            BARA(2, 512);                       // G1 arrive
        }
    } else if (wrp < 8) {
        // ===== warps 4-7: B1 (staggered), A0, A1 =====
        for (int t = 0; t < T_STEPS; ++t) {
            if (t > 0) {
                BARS(2, 512);                   // G1: ghs1(t-1) visible
                B_PHASE(1, t - 1);              // overlaps w0-3's & w8-15's A0
            }
            BARA(5, 384); BARA(6, 256);         // H1a, H1b: h1(t-1) published
            if (t > 0) BARS(4, 256);            // H0b: h0(t-1) ready
            A_PHASE(hb0, paA0);
            BARA(1, 512);                       // G0 arrive
            A_PHASE(hb1, paA1);                 // h1(t-1) valid by own B1 above
        }
        BARS(2, 512);                           // epilogue: last B1
        B_PHASE(1, T_STEPS - 1);
    } else {
        // ===== warps 8-15: A0, A1 only =====
        for (int t = 0; t < T_STEPS; ++t) {
            if (t > 0) BARS(3, 384);            // H0a: h0(t-1) ready
            A_PHASE(hb0, paA0);
            BARA(1, 512);                       // G0 arrive
            BARS(5, 384);                       // H1a: h1(t-1) ready
            A_PHASE(hb1, paA1);
            BARA(2, 512);                       // G1 arrive
        }
    }
}

extern "C" void kernel_launch(void* const* d_in, const int* in_sizes, int n_in,
                              void* d_out, int out_size)
{
    (void)in_sizes; (void)n_in; (void)out_size;
    const float* x    = (const float*)d_in[0];
    const float* Wih  = (const float*)d_in[1];
    const float* Whh  = (const float*)d_in[2];
    const float* bih  = (const float*)d_in[3];
    const float* bhh  = (const float*)d_in[4];
    const float* Wfc  = (const float*)d_in[5];
    const float* bfc  = (const float*)d_in[6];
    float* out = (float*)d_out;

    const size_t smem = (size_t)(2 * HSW + 2 * GHS + 8 + 3 * HID + 5 * HID + 4) * sizeof(float);
    cudaFuncSetAttribute(gru_impute_kernel, cudaFuncAttributeMaxDynamicSharedMemorySize, (int)smem);

    gru_impute_kernel<<<BATCH / 2, NTHREADS, smem>>>(x, Wih, Whh, bih, bhh, Wfc, bfc, out);
}